// round 14
// baseline (speedup 1.0000x reference)
#include <cuda_runtime.h>
#include <cuda_fp16.h>
#include <cstdint>
#include <cstddef>

// ============================================================================
// WaveletBasis: out[B,O] = haar_basis(x).coeffs + x @ base_weight ; kl = 0
//   B=32768, F=1024, O=64, NB=8
// One fp16 GEMM (fp32 accum) on mma.sync HMMA:
//   out = A[B,8192] * Bm[8192,64] + bias
// Per feature f (8 K-slots), j = clip(floor(8u),0,7), u=(tanh x+1)/2:
//   A slots = [x, s0, s1, s0s1, s2, s1s2, s0s2, s0s1s2]  (signs from bits of j)
//   Bm rows = [bw, c1, R(c2+c3), R(c2-c3), H4-rotated c4..c7 / 2], R=sqrt2/2
//   bias[o] = sum_f coeffs[f,o,0]
// j computed WITHOUT tanh: u >= i/8  <=>  x >= atanh(i/4 - 1).
//
// R11: K-split 4 -> 129.9us (main ~115us ~= sm_103 legacy HMMA floor).
// R12: fp16-acc HMMA regressed (same HW rate as fp32-acc on sm_103) -> revert.
// R13/R14 (R13 bench was an infra failure; unchanged resubmit): 2-stage smem
//      ring, ONE barrier/chunk, gen loads issued before MMA block (latency
//      under tensor work), cp.async B, merged prologues, higher-MLP reduce.
// ============================================================================

static constexpr int FDIM = 1024;
static constexpr int NCHUNK = 128;           // K chunks of 64 (8 features)
static constexpr int NSPLIT = 4;
static constexpr int CH_PER = NCHUNK / NSPLIT;   // 32 chunks per CTA
static constexpr int OUT_ELEMS = 32768 * 64;

#define T1 (-0.9729550745276566f)
#define T2 (-0.5493061443340548f)
#define T3 (-0.2554128118829953f)
#define T5 ( 0.2554128118829953f)
#define T6 ( 0.5493061443340548f)
#define T7 ( 0.9729550745276566f)

// B operand fp16, linear chunk layout: [kt=128][n=64][kp=8] uint4 = 1 MB
__device__ uint4 g_B4[NCHUNK * 512];
__device__ float g_bias[64];
// K-split partial sums: [split][B*O] fp32 = 32 MB scratch
__device__ float g_part[NSPLIT * OUT_ELEMS];

// smem: 2 stages, per stage A (128 x 144B) then B (64 x 144B)
static constexpr int A_BYTES = 128 * 144;        // 18432
static constexpr int B_BYTES = 64 * 144;         // 9216
static constexpr int STG     = A_BYTES + B_BYTES; // 27648
static constexpr int SMEM_TOTAL = 2 * STG;        // 55296

// ---------------------------------------------------------------------------
// Merged prologue: blocks [0,512) build rotated B; blocks [512,576) build bias
// ---------------------------------------------------------------------------
__global__ void wb_prep(const float* __restrict__ coeffs,
                        const float* __restrict__ bw) {
    if (blockIdx.x < 512) {
        int gid = blockIdx.x * 128 + threadIdx.x;   // 65536 = F*O
        int f = gid >> 6;
        int o = gid & 63;
        const float* c = coeffs + (size_t)(f * 64 + o) * 8;
        float c1 = c[1], c2 = c[2], c3 = c[3];
        float c4 = c[4], c5 = c[5], c6 = c[6], c7 = c[7];
        float w = bw[f * 64 + o];
        const float R = 0.70710678118654752f;
        float v[8];
        v[0] = w;
        v[1] = c1;
        v[2] = R * (c2 + c3);
        v[3] = R * (c2 - c3);
        v[4] = 0.5f * (c4 + c5 + c6 + c7);
        v[5] = 0.5f * (c4 - c5 + c6 - c7);
        v[6] = 0.5f * (c4 + c5 - c6 - c7);
        v[7] = 0.5f * (c4 - c5 - c6 + c7);
        unsigned p[4];
#pragma unroll
        for (int i = 0; i < 4; i++) {
            unsigned lo = (unsigned)__half_as_ushort(__float2half(v[2 * i]));
            unsigned hi = (unsigned)__half_as_ushort(__float2half(v[2 * i + 1]));
            p[i] = lo | (hi << 16);
        }
        uint4 pk; pk.x = p[0]; pk.y = p[1]; pk.z = p[2]; pk.w = p[3];
        int kt = f >> 3, fl = f & 7;
        g_B4[kt * 512 + o * 8 + fl] = pk;
    } else {
        __shared__ float red[128];
        int o = blockIdx.x - 512;
        int t = threadIdx.x;
        float s = 0.f;
        for (int f = t; f < FDIM; f += 128)
            s += coeffs[(size_t)(f * 64 + o) * 8];
        red[t] = s;
        __syncthreads();
#pragma unroll
        for (int st = 64; st > 0; st >>= 1) {
            if (t < st) red[t] += red[t + st];
            __syncthreads();
        }
        if (t == 0) g_bias[o] = red[0];
    }
}

// ---------------------------------------------------------------------------
// Main GEMM: 1024 CTAs x 128 threads. CTA = (tile, split). 2-stage smem ring,
// single __syncthreads per chunk. fp32-acc HMMA (R11-verified fragment maps).
// ---------------------------------------------------------------------------
#define LDMX4(R, ADDR)                                                        \
    asm volatile("ldmatrix.sync.aligned.m8n8.x4.shared.b16 {%0,%1,%2,%3}, [%4];" \
                 : "=r"((R)[0]), "=r"((R)[1]), "=r"((R)[2]), "=r"((R)[3])     \
                 : "r"(ADDR))
#define MMA16816(C, A, B0, B1)                                                \
    asm volatile("mma.sync.aligned.m16n8k16.row.col.f32.f16.f16.f32 "         \
                 "{%0,%1,%2,%3}, {%4,%5,%6,%7}, {%8,%9}, {%0,%1,%2,%3};"      \
                 : "+f"((C)[0]), "+f"((C)[1]), "+f"((C)[2]), "+f"((C)[3])     \
                 : "r"((A)[0]), "r"((A)[1]), "r"((A)[2]), "r"((A)[3]),        \
                   "r"(B0), "r"(B1))
#define CP_ASYNC16(DST, SRC)                                                  \
    asm volatile("cp.async.cg.shared.global [%0], [%1], 16;"                  \
                 :: "r"(DST), "l"(SRC) : "memory")
#define CP_COMMIT()  asm volatile("cp.async.commit_group;" ::: "memory")
#define CP_WAIT0()   asm volatile("cp.async.wait_group 0;" ::: "memory")
#define STS128(r0, r1, r2, r3, addr)                                          \
    asm volatile("st.shared.v4.b32 [%0], {%1, %2, %3, %4};"                   \
                 :: "r"(addr), "r"(r0), "r"(r1), "r"(r2), "r"(r3) : "memory")

__device__ __forceinline__ uint4 wb_pack(float xs) {
    bool b2 = xs >= 0.0f;
    bool b1 = xs >= (b2 ? T6 : T2);
    bool b0 = xs >= (b2 ? (b1 ? T7 : T5) : (b1 ? T3 : T1));
    unsigned s0 = b2 ? 0x8000u : 0u;
    unsigned s1 = b1 ? 0x8000u : 0u;
    unsigned s2 = b0 ? 0x8000u : 0u;
    const unsigned ONE = 0x3C00u;
    unsigned hx = (unsigned)__half_as_ushort(__float2half(xs));
    uint4 pk;
    pk.x = hx | ((ONE | s0) << 16);
    pk.y = (ONE | s1) | ((ONE | (s0 ^ s1)) << 16);
    pk.z = (ONE | s2) | ((ONE | (s1 ^ s2)) << 16);
    pk.w = (ONE | (s0 ^ s2)) | ((ONE | (s0 ^ s1 ^ s2)) << 16);
    return pk;
}

__device__ __forceinline__ void wb_sts8(uint32_t a_sts, float4 xv) {
    float xa[4] = {xv.x, xv.y, xv.z, xv.w};
#pragma unroll
    for (int i = 0; i < 4; i++) {
        uint4 pk = wb_pack(xa[i]);
        STS128(pk.x, pk.y, pk.z, pk.w, a_sts + i * 16);
    }
}

__global__ void __launch_bounds__(128, 4)
wb_main(const float* __restrict__ x) {
    extern __shared__ __align__(128) char smem[];
    const uint32_t sb = (uint32_t)__cvta_generic_to_shared(smem);

    const int t = threadIdx.x;
    const int w = t >> 5;
    const int l = t & 31;
    const int tile  = blockIdx.x & 255;
    const int split = blockIdx.x >> 8;
    const int kt0 = split * CH_PER;

    float acc[2][8][4];
#pragma unroll
    for (int g = 0; g < 2; g++)
#pragma unroll
        for (int nb = 0; nb < 8; nb++)
#pragma unroll
            for (int i = 0; i < 4; i++) acc[g][nb][i] = 0.f;

    // ---- producer addressing (R11 map + stage offset) ----
    // thread t handles (row=t>>1, half=t&1) and (row+64, half)
    const float* px0 = x + (size_t)(tile * 128 + (t >> 1)) * FDIM + (t & 1) * 4;
    const float* px1 = px0 + (size_t)64 * FDIM;
    const uint32_t a_sts0 = sb + (uint32_t)((t >> 1) * 144 + (t & 1) * 64);
    const uint32_t a_sts1 = a_sts0 + 64 * 144;
    // B cp.async dests: id = t + j*128 -> (n = id>>3, kp = id&7)
    uint32_t b_dst[4];
#pragma unroll
    for (int j = 0; j < 4; j++) {
        int id = t + j * 128;
        b_dst[j] = sb + (uint32_t)(A_BYTES + (id >> 3) * 144 + (id & 7) * 16);
    }

    // ---- consumer addressing (R11/R7 verified maps, offsets within stage) --
    const uint32_t a_off0 = (uint32_t)((w * 32 + (l & 15)) * 144 + (l >> 4) * 16);
    const uint32_t a_off1 = a_off0 + 16 * 144;
    uint32_t b_off[4];
#pragma unroll
    for (int p = 0; p < 4; p++)
        b_off[p] = (uint32_t)(A_BYTES +
                              (p * 16 + ((l >> 4) << 3) + (l & 7)) * 144 +
                              ((l >> 3) & 1) * 16);

    // ---- prologue: fill stage 0 with chunk kt0 ----
#pragma unroll
    for (int j = 0; j < 4; j++)
        CP_ASYNC16(b_dst[j], (const void*)(g_B4 + kt0 * 512 + t + j * 128));
    CP_COMMIT();
    wb_sts8(a_sts0, *(const float4*)(px0 + kt0 * 8));
    wb_sts8(a_sts1, *(const float4*)(px1 + kt0 * 8));
    CP_WAIT0();
    __syncthreads();

    // ---- main loop: one barrier per chunk, 2-stage ring ----
#pragma unroll 1
    for (int ki = 0; ki < CH_PER; ki++) {
        const uint32_t cur = sb + (uint32_t)((ki & 1) * STG);
        const uint32_t nxt = sb + (uint32_t)(((ki + 1) & 1) * STG);
        const int ktn = kt0 + ki + 1;

        // issue next chunk's global loads BEFORE the MMA block
        float4 xv0, xv1;
        const bool more = (ki + 1 < CH_PER);
        if (more) {
#pragma unroll
            for (int j = 0; j < 4; j++)
                CP_ASYNC16(b_dst[j] + (nxt - sb),
                           (const void*)(g_B4 + ktn * 512 + t + j * 128));
            xv0 = *(const float4*)(px0 + ktn * 8);
            xv1 = *(const float4*)(px1 + ktn * 8);
        }
        CP_COMMIT();

        // ---- compute chunk ki from cur (latency of loads hides here) ----
#pragma unroll
        for (int ks = 0; ks < 4; ks++) {
            const uint32_t koff = (uint32_t)(ks * 32);
            uint32_t a0[4], a1[4], bf[4][4];
            LDMX4(a0, cur + a_off0 + koff);
            LDMX4(a1, cur + a_off1 + koff);
#pragma unroll
            for (int p = 0; p < 4; p++) LDMX4(bf[p], cur + b_off[p] + koff);
#pragma unroll
            for (int p = 0; p < 4; p++) {
                MMA16816(acc[0][2 * p],     a0, bf[p][0], bf[p][1]);
                MMA16816(acc[1][2 * p],     a1, bf[p][0], bf[p][1]);
                MMA16816(acc[0][2 * p + 1], a0, bf[p][2], bf[p][3]);
                MMA16816(acc[1][2 * p + 1], a1, bf[p][2], bf[p][3]);
            }
        }

        // ---- pack + store next A tile (x data arrived during MMA) ----
        if (more) {
            wb_sts8(a_sts0 + (nxt - sb), xv0);
            wb_sts8(a_sts1 + (nxt - sb), xv1);
        }
        CP_WAIT0();
        __syncthreads();
    }

    // ---- epilogue: store fp32 partials (bias added in reduce) ----
    float* part = g_part + (size_t)split * OUT_ELEMS;
    const int col0 = (l & 3) * 2;
#pragma unroll
    for (int g = 0; g < 2; g++) {
        int row0 = tile * 128 + w * 32 + g * 16 + (l >> 2);
#pragma unroll
        for (int nb = 0; nb < 8; nb++) {
            float2 v0, v1;
            v0.x = acc[g][nb][0];
            v0.y = acc[g][nb][1];
            v1.x = acc[g][nb][2];
            v1.y = acc[g][nb][3];
            *(float2*)(part + (size_t)row0 * 64 + nb * 8 + col0) = v0;
            *(float2*)(part + (size_t)(row0 + 8) * 64 + nb * 8 + col0) = v1;
        }
    }
}

// ---------------------------------------------------------------------------
// Reduce: out = sum(partials) + bias ; zero kl tail. 2 float4 per thread.
// ---------------------------------------------------------------------------
__global__ void wb_reduce(float* __restrict__ out, int out_size) {
    int i0 = (blockIdx.x * blockDim.x + threadIdx.x) * 2;   // float4 index
    const float4* p = (const float4*)g_part;
#pragma unroll
    for (int u = 0; u < 2; u++) {
        int i = i0 + u;
        float4 v0 = p[i];
        float4 v1 = p[i + OUT_ELEMS / 4];
        float4 v2 = p[i + 2 * (OUT_ELEMS / 4)];
        float4 v3 = p[i + 3 * (OUT_ELEMS / 4)];
        const float4 bv = *(const float4*)&g_bias[(i * 4) & 63];
        float4 r;
        r.x = (v0.x + v1.x) + (v2.x + v3.x) + bv.x;
        r.y = (v0.y + v1.y) + (v2.y + v3.y) + bv.y;
        r.z = (v0.z + v1.z) + (v2.z + v3.z) + bv.z;
        r.w = (v0.w + v1.w) + (v2.w + v3.w) + bv.w;
        ((float4*)out)[i] = r;
    }
    if (blockIdx.x == 0 && threadIdx.x == 0) {
        for (int k = OUT_ELEMS; k < out_size; k++) out[k] = 0.f;
    }
}

// ---------------------------------------------------------------------------
extern "C" void kernel_launch(void* const* d_in, const int* in_sizes, int n_in,
                              void* d_out, int out_size) {
    const float* x      = (const float*)d_in[0];   // [32768,1024] f32
    const float* coeffs = (const float*)d_in[1];   // [1024,64,8]  f32
    const float* bw     = (const float*)d_in[2];   // [1024,64]    f32
    float* out = (float*)d_out;

    cudaFuncSetAttribute(wb_main, cudaFuncAttributeMaxDynamicSharedMemorySize,
                         SMEM_TOTAL);

    wb_prep<<<576, 128>>>(coeffs, bw);
    wb_main<<<256 * NSPLIT, 128, SMEM_TOTAL>>>(x);
    wb_reduce<<<OUT_ELEMS / 8 / 256, 256>>>(out, out_size);
}

// round 15
// speedup vs baseline: 1.3694x; 1.3694x over previous
#include <cuda_runtime.h>
#include <cuda_fp16.h>
#include <cstdint>
#include <cstddef>

// ============================================================================
// WaveletBasis: out[B,O] = haar_basis(x).coeffs + x @ base_weight ; kl = 0
//   B=32768, F=1024, O=64, NB=8
// One fp16 GEMM (fp32 accum) on mma.sync HMMA:
//   out = A[B,8192] * Bm[8192,64] + bias
// Per feature f (8 K-slots), j = clip(floor(8u),0,7), u=(tanh x+1)/2:
//   A slots = [x, s0, s1, s0s1, s2, s1s2, s0s2, s0s1s2]  (signs from bits of j)
//   Bm rows = [bw, c1, R(c2+c3), R(c2-c3), H4-rotated c4..c7 / 2], R=sqrt2/2
//   bias[o] = sum_f coeffs[f,o,0]
// j computed WITHOUT tanh: u >= i/8  <=>  x >= atanh(i/4 - 1).
//
// R11: K-split 4 -> 129.9us.  R12: fp16-acc regressed (+14us of instructions
// on an issue-bound loop -> evidence main is ISSUE-bound, not tensor-bound).
// R14: 2-stage/1-barrier ring regressed (wait_group 0 drained the prefetch).
// R15: exact R11 skeleton; gen_A sign-pack via 8-entry SMEM LUT (the three
//      sign words + q0-high are pure functions of the 3-bit bucket j) ->
//      ~220 fewer issue-cycles/SMSP/chunk; coalesced 2x float4 reduce.
// ============================================================================

static constexpr int FDIM = 1024;
static constexpr int NCHUNK = 128;           // K chunks of 64 (8 features)
static constexpr int NSPLIT = 4;
static constexpr int CH_PER = NCHUNK / NSPLIT;   // 32 chunks per CTA
static constexpr int OUT_ELEMS = 32768 * 64;

#define T1 (-0.9729550745276566f)
#define T2 (-0.5493061443340548f)
#define T3 (-0.2554128118829953f)
#define T5 ( 0.2554128118829953f)
#define T6 ( 0.5493061443340548f)
#define T7 ( 0.9729550745276566f)

// B operand fp16, linear chunk layout: [kt=128][n=64][kp=8] uint4 = 1 MB
__device__ uint4 g_B4[NCHUNK * 512];
__device__ float g_bias[64];
// K-split partial sums: [split][B*O] fp32 = 32 MB scratch
__device__ float g_part[NSPLIT * OUT_ELEMS];

// ---------------------------------------------------------------------------
// Prologue 1: rotated B matrix (fp16)
// ---------------------------------------------------------------------------
__global__ void wb_prep_B(const float* __restrict__ coeffs,
                          const float* __restrict__ bw) {
    int gid = blockIdx.x * blockDim.x + threadIdx.x;   // 65536 = F*O
    int f = gid >> 6;
    int o = gid & 63;
    const float* c = coeffs + (size_t)(f * 64 + o) * 8;
    float c1 = c[1], c2 = c[2], c3 = c[3];
    float c4 = c[4], c5 = c[5], c6 = c[6], c7 = c[7];
    float w = bw[f * 64 + o];
    const float R = 0.70710678118654752f;
    float v[8];
    v[0] = w;
    v[1] = c1;
    v[2] = R * (c2 + c3);
    v[3] = R * (c2 - c3);
    v[4] = 0.5f * (c4 + c5 + c6 + c7);
    v[5] = 0.5f * (c4 - c5 + c6 - c7);
    v[6] = 0.5f * (c4 + c5 - c6 - c7);
    v[7] = 0.5f * (c4 - c5 - c6 + c7);
    unsigned p[4];
#pragma unroll
    for (int i = 0; i < 4; i++) {
        unsigned lo = (unsigned)__half_as_ushort(__float2half(v[2 * i]));
        unsigned hi = (unsigned)__half_as_ushort(__float2half(v[2 * i + 1]));
        p[i] = lo | (hi << 16);
    }
    uint4 pk; pk.x = p[0]; pk.y = p[1]; pk.z = p[2]; pk.w = p[3];
    int kt = f >> 3, fl = f & 7;
    g_B4[kt * 512 + o * 8 + fl] = pk;
}

// ---------------------------------------------------------------------------
// Prologue 2: bias[o] = sum_f coeffs[f,o,0]   (deterministic tree reduce)
// ---------------------------------------------------------------------------
__global__ void wb_prep_bias(const float* __restrict__ coeffs) {
    __shared__ float red[128];
    int o = blockIdx.x;
    int t = threadIdx.x;
    float s = 0.f;
    for (int f = t; f < FDIM; f += 128)
        s += coeffs[(size_t)(f * 64 + o) * 8];
    red[t] = s;
    __syncthreads();
#pragma unroll
    for (int st = 64; st > 0; st >>= 1) {
        if (t < st) red[t] += red[t + st];
        __syncthreads();
    }
    if (t == 0) g_bias[o] = red[0];
}

// ---------------------------------------------------------------------------
// Main GEMM: 1024 CTAs x 128 threads. CTA = (tile, split):
//   tile = bx & 255 -> rows tile*128..+128 ; split = bx >> 8 -> chunks
//   split*32..+32. Warp handles 32 rows (two m16 groups) x N=64.
// Sign packing via 8-entry smem LUT (indexed by bucket j).
// ---------------------------------------------------------------------------
#define LDMX4(R, ADDR)                                                        \
    asm volatile("ldmatrix.sync.aligned.m8n8.x4.shared.b16 {%0,%1,%2,%3}, [%4];" \
                 : "=r"((R)[0]), "=r"((R)[1]), "=r"((R)[2]), "=r"((R)[3])     \
                 : "r"(ADDR))
#define MMA16816(C, A, B0, B1)                                                \
    asm volatile("mma.sync.aligned.m16n8k16.row.col.f32.f16.f16.f32 "         \
                 "{%0,%1,%2,%3}, {%4,%5,%6,%7}, {%8,%9}, {%0,%1,%2,%3};"      \
                 : "+f"((C)[0]), "+f"((C)[1]), "+f"((C)[2]), "+f"((C)[3])     \
                 : "r"((A)[0]), "r"((A)[1]), "r"((A)[2]), "r"((A)[3]),        \
                   "r"(B0), "r"(B1))

__global__ void __launch_bounds__(128, 4)
wb_main(const float* __restrict__ x) {
    __shared__ __half As[128][72];   // padded 144 B stride: conflict-free
    __shared__ __half Bs[64][72];
    __shared__ uint4 lut[8];         // sign words per bucket j

    const int t = threadIdx.x;
    const int w = t >> 5;
    const int l = t & 31;
    const int tile  = blockIdx.x & 255;
    const int split = blockIdx.x >> 8;
    const int kt0 = split * CH_PER;

    // ---- build the sign LUT (once per CTA) ----
    if (t < 8) {
        const unsigned ONE = 0x3C00u;
        unsigned s0 = (t & 4) ? 0x8000u : 0u;
        unsigned s1 = (t & 2) ? 0x8000u : 0u;
        unsigned s2 = (t & 1) ? 0x8000u : 0u;
        uint4 e;
        e.x = (ONE | s0) << 16;                                  // q0 high half
        e.y = (ONE | s1) | ((ONE | (s0 ^ s1)) << 16);
        e.z = (ONE | s2) | ((ONE | (s1 ^ s2)) << 16);
        e.w = (ONE | (s0 ^ s2)) | ((ONE | (s0 ^ s1 ^ s2)) << 16);
        lut[t] = e;
    }

    float acc[2][8][4];
#pragma unroll
    for (int g = 0; g < 2; g++)
#pragma unroll
        for (int nb = 0; nb < 8; nb++)
#pragma unroll
            for (int i = 0; i < 4; i++) acc[g][nb][i] = 0.f;

    // A fragment addresses (verified R4/R11 mapping)
    uint32_t a_addr0 = (uint32_t)__cvta_generic_to_shared(
        &As[w * 32 + (l & 15)][(l >> 4) * 8]);
    uint32_t a_addr1 = (uint32_t)__cvta_generic_to_shared(
        &As[w * 32 + 16 + (l & 15)][(l >> 4) * 8]);
    // B fragment addresses via x4 n-pairs (verified R7/R11 mapping)
    const uint32_t bs_base = (uint32_t)__cvta_generic_to_shared(&Bs[0][0]);
    uint32_t b_off[4];
#pragma unroll
    for (int p = 0; p < 4; p++)
        b_off[p] = bs_base + (uint32_t)((p * 16 + ((l >> 4) << 3) + (l & 7)) * 144 +
                                        ((l >> 3) & 1) * 16);

    const char* lut_bytes = (const char*)lut;

    for (int ki = 0; ki < CH_PER; ki++) {
        const int kt = kt0 + ki;
        __syncthreads();  // prev compute done; also covers initial LUT build

        // ---- generate A chunk: rows 0..127, 8 features (LUT pack) ----
#pragma unroll
        for (int j = 0; j < 2; j++) {
            int id = t + j * 128;
            int row = id >> 1, half = id & 1;
            const float4 xv = *(const float4*)(
                x + (size_t)(tile * 128 + row) * FDIM + kt * 8 + half * 4);
            float xa[4] = {xv.x, xv.y, xv.z, xv.w};
#pragma unroll
            for (int i = 0; i < 4; i++) {
                float xs = xa[i];
                bool b2 = xs >= 0.0f;
                bool b1 = xs >= (b2 ? T6 : T2);
                bool b0 = xs >= (b2 ? (b1 ? T7 : T5) : (b1 ? T3 : T1));
                int off = (b2 ? 64 : 0) + (b1 ? 32 : 0) + (b0 ? 16 : 0);
                const uint4 lv = *(const uint4*)(lut_bytes + off);
                unsigned hx = (unsigned)__half_as_ushort(__float2half(xs));
                uint4 pk;
                pk.x = lv.x | hx;
                pk.y = lv.y;
                pk.z = lv.z;
                pk.w = lv.w;
                *(uint4*)&As[row][(half * 4 + i) * 8] = pk;
            }
        }

        // ---- copy B chunk: 512 uint4 ----
#pragma unroll
        for (int j = 0; j < 4; j++) {
            int id = t + j * 128;
            int n = id >> 3, kp = id & 7;
            *(uint4*)&Bs[n][kp * 8] = g_B4[(kt * 64 + n) * 8 + kp];
        }

        __syncthreads();

        // ---- compute: 4 k16 steps ----
#pragma unroll
        for (int ks = 0; ks < 4; ks++) {
            const uint32_t koff = (uint32_t)(ks * 32);
            uint32_t a0[4], a1[4], bf[4][4];
            LDMX4(a0, a_addr0 + koff);
            LDMX4(a1, a_addr1 + koff);
#pragma unroll
            for (int p = 0; p < 4; p++) LDMX4(bf[p], b_off[p] + koff);
#pragma unroll
            for (int p = 0; p < 4; p++) {
                MMA16816(acc[0][2 * p],     a0, bf[p][0], bf[p][1]);
                MMA16816(acc[1][2 * p],     a1, bf[p][0], bf[p][1]);
                MMA16816(acc[0][2 * p + 1], a0, bf[p][2], bf[p][3]);
                MMA16816(acc[1][2 * p + 1], a1, bf[p][2], bf[p][3]);
            }
        }
    }

    // ---- epilogue: store fp32 partials (bias added in reduce) ----
    float* part = g_part + (size_t)split * OUT_ELEMS;
    const int col0 = (l & 3) * 2;
#pragma unroll
    for (int g = 0; g < 2; g++) {
        int row0 = tile * 128 + w * 32 + g * 16 + (l >> 2);
#pragma unroll
        for (int nb = 0; nb < 8; nb++) {
            float2 v0, v1;
            v0.x = acc[g][nb][0];
            v0.y = acc[g][nb][1];
            v1.x = acc[g][nb][2];
            v1.y = acc[g][nb][3];
            *(float2*)(part + (size_t)row0 * 64 + nb * 8 + col0) = v0;
            *(float2*)(part + (size_t)(row0 + 8) * 64 + nb * 8 + col0) = v1;
        }
    }
}

// ---------------------------------------------------------------------------
// Reduce: out = sum(partials) + bias ; zero kl tail. 2 coalesced float4/thread.
// ---------------------------------------------------------------------------
__global__ void wb_reduce(float* __restrict__ out, int out_size) {
    const int gid = blockIdx.x * blockDim.x + threadIdx.x;
    const float4* p = (const float4*)g_part;
#pragma unroll
    for (int u = 0; u < 2; u++) {
        int i = gid + u * (OUT_ELEMS / 8);         // coalesced halves
        float4 v0 = p[i];
        float4 v1 = p[i + OUT_ELEMS / 4];
        float4 v2 = p[i + 2 * (OUT_ELEMS / 4)];
        float4 v3 = p[i + 3 * (OUT_ELEMS / 4)];
        const float4 bv = *(const float4*)&g_bias[(i * 4) & 63];
        float4 r;
        r.x = (v0.x + v1.x) + (v2.x + v3.x) + bv.x;
        r.y = (v0.y + v1.y) + (v2.y + v3.y) + bv.y;
        r.z = (v0.z + v1.z) + (v2.z + v3.z) + bv.z;
        r.w = (v0.w + v1.w) + (v2.w + v3.w) + bv.w;
        ((float4*)out)[i] = r;
    }
    if (blockIdx.x == 0 && threadIdx.x == 0) {
        for (int k = OUT_ELEMS; k < out_size; k++) out[k] = 0.f;
    }
}

// ---------------------------------------------------------------------------
extern "C" void kernel_launch(void* const* d_in, const int* in_sizes, int n_in,
                              void* d_out, int out_size) {
    const float* x      = (const float*)d_in[0];   // [32768,1024] f32
    const float* coeffs = (const float*)d_in[1];   // [1024,64,8]  f32
    const float* bw     = (const float*)d_in[2];   // [1024,64]    f32
    float* out = (float*)d_out;

    wb_prep_B<<<512, 128>>>(coeffs, bw);
    wb_prep_bias<<<64, 128>>>(coeffs);
    wb_main<<<256 * NSPLIT, 128>>>(x);
    wb_reduce<<<OUT_ELEMS / 8 / 256, 256>>>(out, out_size);
}